// round 1
// baseline (speedup 1.0000x reference)
#include <cuda_runtime.h>
#include <math.h>

#define TPB 256
#define NSTATE 4

__global__ __launch_bounds__(TPB) void pmsn_kernel(
    const float* __restrict__ log_dt,
    const float* __restrict__ log_A_real,
    const float* __restrict__ A_imag,
    const float* __restrict__ VinvB_real,
    const float* __restrict__ VinvB_imag,
    const float* __restrict__ CV_real,
    const float* __restrict__ CV_imag,
    float* __restrict__ out, int L)
{
    const int h = blockIdx.x;
    const int t = threadIdx.x;
    const float dt = expf(log_dt[h]);

    float vr[NSTATE], vi[NSTATE], Rr[NSTATE], Ri[NSTATE];

    const double TWO_PI     = 6.283185307179586476925286766559;
    const double INV_TWO_PI = 0.15915494309189533576888376337251;

#pragma unroll
    for (int n = 0; n < NSTATE; ++n) {
        const int idx = h * NSTATE + n;
        const float Are = -expf(log_A_real[idx]);
        const float Aim = A_imag[idx];
        const float adr = Are * dt;        // Re(A*dt)
        const float adi = Aim * dt;        // Im(A*dt)

        // A_bar = exp(adr + i*adi)
        float sb, cb;
        sincosf(adi, &sb, &cb);
        const float eb  = expf(adr);
        const float abr = eb * cb;
        const float abi = eb * sb;

        // 1/A = conj(A)/|A|^2
        const float inv = 1.0f / (Are * Are + Aim * Aim);
        const float iAr =  Are * inv;
        const float iAi = -Aim * inv;

        // q = (A_bar - 1) / A
        const float mr = abr - 1.0f;
        const float mi = abi;
        const float qr = mr * iAr - mi * iAi;
        const float qi = mr * iAi + mi * iAr;

        // B_bar = q * B
        const float Br = VinvB_real[idx], Bi = VinvB_imag[idx];
        const float bbr = qr * Br - qi * Bi;
        const float bbi = qr * Bi + qi * Br;

        // coef = C * B_bar
        const float Cr = CV_real[idx], Ci = CV_imag[idx];
        const float kr = Cr * bbr - Ci * bbi;
        const float ki = Cr * bbi + Ci * bbr;

        // start state w = exp(Adt * t)   (phase reduced in double)
        double ph = (double)adi * (double)t;
        ph -= floor(ph * INV_TWO_PI) * TWO_PI;
        float sw, cw;
        sincosf((float)ph, &sw, &cw);
        const float mag = expf(adr * (float)t);
        const float wr = mag * cw;
        const float wi = mag * sw;

        // v = coef * w  (coefficient folded into the state)
        vr[n] = kr * wr - ki * wi;
        vi[n] = kr * wi + ki * wr;

        // stride ratio R = A_bar^TPB  (computed directly, not by squaring chain)
        double phR = (double)adi * (double)TPB;
        phR -= floor(phR * INV_TWO_PI) * TWO_PI;
        float sR, cR;
        sincosf((float)phR, &sR, &cR);
        const float magR = expf(adr * (float)TPB);
        Rr[n] = magR * cR;
        Ri[n] = magR * sR;
    }

    float* __restrict__ orow = out + (size_t)h * (size_t)L;
#pragma unroll 4
    for (int l = t; l < L; l += TPB) {
        orow[l] = (vr[0] + vr[1]) + (vr[2] + vr[3]);
#pragma unroll
        for (int n = 0; n < NSTATE; ++n) {
            const float nr = vr[n] * Rr[n] - vi[n] * Ri[n];
            const float ni = vr[n] * Ri[n] + vi[n] * Rr[n];
            vr[n] = nr;
            vi[n] = ni;
        }
    }
}

extern "C" void kernel_launch(void* const* d_in, const int* in_sizes, int n_in,
                              void* d_out, int out_size) {
    const float* log_dt     = (const float*)d_in[0];
    const float* log_A_real = (const float*)d_in[1];
    const float* A_imag     = (const float*)d_in[2];
    const float* VinvB_real = (const float*)d_in[3];
    const float* VinvB_imag = (const float*)d_in[4];
    const float* CV_real    = (const float*)d_in[5];
    const float* CV_imag    = (const float*)d_in[6];
    const int H = in_sizes[0];               // 2048
    const int L = out_size / H;              // 4096
    pmsn_kernel<<<H, TPB>>>(log_dt, log_A_real, A_imag, VinvB_real, VinvB_imag,
                            CV_real, CV_imag, (float*)d_out, L);
}

// round 2
// speedup vs baseline: 3.6537x; 3.6537x over previous
#include <cuda_runtime.h>
#include <math.h>

#define TPB 128
#define NSTATE 4
#define NBITS 7          // TPB = 2^NBITS
#define KTAB 8           // k = 0..6 bit powers, k = 7 is stride ratio A_bar^TPB

__device__ __forceinline__ float2 cmul(float2 a, float2 b) {
    return make_float2(a.x * b.x - a.y * b.y, a.x * b.y + a.y * b.x);
}

__global__ __launch_bounds__(TPB) void pmsn_kernel(
    const float* __restrict__ log_dt,
    const float* __restrict__ log_A_real,
    const float* __restrict__ A_imag,
    const float* __restrict__ VinvB_real,
    const float* __restrict__ VinvB_imag,
    const float* __restrict__ CV_real,
    const float* __restrict__ CV_imag,
    float* __restrict__ out, int L)
{
    const int h = blockIdx.x;
    const int t = threadIdx.x;

    __shared__ float2 Psm[NSTATE][KTAB];   // Psm[n][k] = exp(Adt * 2^k)
    __shared__ float2 coef_sm[NSTATE];     // C * B_bar

    if (t < NSTATE * KTAB) {
        const int n = t >> 3;
        const int k = t & 7;
        const int idx = h * NSTATE + n;

        const float dt  = expf(log_dt[h]);
        const float Are = -expf(log_A_real[idx]);
        const float Aim = A_imag[idx];
        const float adr = Are * dt;
        const float adi = Aim * dt;

        // P = exp(Adt * 2^k), phase reduced in double (exact; only 32 lanes pay)
        const double TWO_PI     = 6.283185307179586476925286766559;
        const double INV_TWO_PI = 0.15915494309189533576888376337251;
        const float  pw = (float)(1 << k);
        double ph = (double)adi * (double)(1 << k);
        ph -= floor(ph * INV_TWO_PI) * TWO_PI;
        float s, c;
        sincosf((float)ph, &s, &c);
        const float m = expf(adr * pw);
        Psm[n][k] = make_float2(m * c, m * s);

        if (k == 0) {
            // A_bar = exp(Adt) is this lane's P
            const float abr = m * c;
            const float abi = m * s;
            // q = (A_bar - 1) / A
            const float inv = 1.0f / (Are * Are + Aim * Aim);
            const float iAr =  Are * inv;
            const float iAi = -Aim * inv;
            const float mr = abr - 1.0f, mi = abi;
            const float qr = mr * iAr - mi * iAi;
            const float qi = mr * iAi + mi * iAr;
            // B_bar = q * B ;  coef = C * B_bar
            const float Br = VinvB_real[idx], Bi = VinvB_imag[idx];
            const float bbr = qr * Br - qi * Bi;
            const float bbi = qr * Bi + qi * Br;
            const float Cr = CV_real[idx], Ci = CV_imag[idx];
            coef_sm[n] = make_float2(Cr * bbr - Ci * bbi, Cr * bbi + Ci * bbr);
        }
    }
    __syncthreads();

    // v[n] = coef[n] * A_bar^t via bit-product (pure FMA, no transcendentals)
    float2 v[NSTATE], R[NSTATE];
#pragma unroll
    for (int n = 0; n < NSTATE; ++n) {
        v[n] = coef_sm[n];
        R[n] = Psm[n][KTAB - 1];           // A_bar^TPB
    }
#pragma unroll
    for (int k = 0; k < NBITS; ++k) {
        if ((t >> k) & 1) {
#pragma unroll
            for (int n = 0; n < NSTATE; ++n)
                v[n] = cmul(v[n], Psm[n][k]);
        }
    }

    // main recurrence: out[l] = sum_n Re(v[n]);  v *= R
    float* __restrict__ orow = out + (size_t)h * (size_t)L;
#pragma unroll 8
    for (int l = t; l < L; l += TPB) {
        orow[l] = (v[0].x + v[1].x) + (v[2].x + v[3].x);
#pragma unroll
        for (int n = 0; n < NSTATE; ++n)
            v[n] = cmul(v[n], R[n]);
    }
}

extern "C" void kernel_launch(void* const* d_in, const int* in_sizes, int n_in,
                              void* d_out, int out_size) {
    const float* log_dt     = (const float*)d_in[0];
    const float* log_A_real = (const float*)d_in[1];
    const float* A_imag     = (const float*)d_in[2];
    const float* VinvB_real = (const float*)d_in[3];
    const float* VinvB_imag = (const float*)d_in[4];
    const float* CV_real    = (const float*)d_in[5];
    const float* CV_imag    = (const float*)d_in[6];
    const int H = in_sizes[0];               // 2048
    const int L = out_size / H;              // 4096
    pmsn_kernel<<<H, TPB>>>(log_dt, log_A_real, A_imag, VinvB_real, VinvB_imag,
                            CV_real, CV_imag, (float*)d_out, L);
}

// round 3
// speedup vs baseline: 4.2306x; 1.1579x over previous
#include <cuda_runtime.h>
#include <math.h>

#define TPB 128
#define NSTATE 4
#define NPAIR 2          // state pairs packed in f32x2
#define NPHASE 4         // consecutive l per thread -> STG.128
#define NBITS 7          // TPB = 2^7

typedef unsigned long long ull;

__device__ __forceinline__ ull pk2(float lo, float hi) {
    ull r; asm("mov.b64 %0, {%1,%2};" : "=l"(r) : "f"(lo), "f"(hi)); return r;
}
__device__ __forceinline__ float2 unpk2(ull v) {
    float2 f; asm("mov.b64 {%0,%1}, %2;" : "=f"(f.x), "=f"(f.y) : "l"(v)); return f;
}
__device__ __forceinline__ ull mul2(ull a, ull b) {
    ull r; asm("mul.rn.f32x2 %0, %1, %2;" : "=l"(r) : "l"(a), "l"(b)); return r;
}
__device__ __forceinline__ ull fma2(ull a, ull b, ull c) {
    ull r; asm("fma.rn.f32x2 %0, %1, %2, %3;" : "=l"(r) : "l"(a), "l"(b), "l"(c)); return r;
}
__device__ __forceinline__ ull add2(ull a, ull b) {
    ull r; asm("add.rn.f32x2 %0, %1, %2;" : "=l"(r) : "l"(a), "l"(b)); return r;
}

__global__ __launch_bounds__(TPB) void pmsn_kernel(
    const float* __restrict__ log_dt,
    const float* __restrict__ log_A_real,
    const float* __restrict__ A_imag,
    const float* __restrict__ VinvB_real,
    const float* __restrict__ VinvB_imag,
    const float* __restrict__ CV_real,
    const float* __restrict__ CV_imag,
    float* __restrict__ out, int L)
{
    const int h = blockIdx.x;
    const int t = threadIdx.x;
    const int STRIDE = NPHASE * TPB;          // 512: recurrence stride in l

    // smem tables (pair-packed along last dim; 8B-aligned for ull loads)
    __shared__ __align__(8) float Pr[NBITS][NSTATE], Pi[NBITS][NSTATE]; // A_bar^(4*2^k)
    __shared__ __align__(8) float Sr[NSTATE], Si[NSTATE];               // A_bar^512
    __shared__ __align__(8) float Ps[NSTATE], Qs[NSTATE];               // 2Re(R), -|R|^2
    __shared__ __align__(8) float Cc[NPHASE][NSTATE], Cs[NPHASE][NSTATE]; // Re/-Im of A_bar^i (i=1..3; [0] unused)
    __shared__ __align__(8) float Kr[NSTATE], Ki[NSTATE];               // coef = C*B_bar

    // ---- prologue writers: 44 lanes, each one transcendental bundle ----
    if (t < NSTATE * 11) {
        const int n = t / 11;
        const int j = t % 11;
        const int e = (j < 7) ? (4 << j) : (j == 7 ? STRIDE : (j - 7)); // exponent
        const int idx = h * NSTATE + n;

        const float dt  = expf(log_dt[h]);
        const float Are = -expf(log_A_real[idx]);
        const float Aim = A_imag[idx];
        const float adr = Are * dt;
        const float adi = Aim * dt;

        const double TWO_PI     = 6.283185307179586476925286766559;
        const double INV_TWO_PI = 0.15915494309189533576888376337251;
        double ph = (double)adi * (double)e;
        ph -= floor(ph * INV_TWO_PI) * TWO_PI;
        float s, c;
        sincosf((float)ph, &s, &c);
        const float m  = expf(adr * (float)e);
        const float re = m * c, im = m * s;

        if (j < 7) { Pr[j][n] = re; Pi[j][n] = im; }
        else if (j == 7) {
            Sr[n] = re; Si[n] = im;
            Ps[n] = re + re;
            Qs[n] = -(re * re + im * im);
        } else {
            Cc[j - 7][n] = re; Cs[j - 7][n] = -im;   // store -sin for fused extraction
            if (j == 8) {
                // this lane holds A_bar = exp(Adt); build coef = C * (A_bar-1)/A * B
                const float inv = 1.0f / (Are * Are + Aim * Aim);
                const float iAr =  Are * inv, iAi = -Aim * inv;
                const float mr = re - 1.0f, mi = im;
                const float qr = mr * iAr - mi * iAi;
                const float qi = mr * iAi + mi * iAr;
                const float Br = VinvB_real[idx], Bi = VinvB_imag[idx];
                const float bbr = qr * Br - qi * Bi;
                const float bbi = qr * Bi + qi * Br;
                const float Cr = CV_real[idx], Ci = CV_imag[idx];
                Kr[n] = Cr * bbr - Ci * bbi;
                Ki[n] = Cr * bbi + Ci * bbr;
            }
        }
    }
    __syncthreads();

    // ---- per-thread start: v = coef * A_bar^(4t)  (pair-packed bit product) ----
    ull vr[NPAIR], vi[NPAIR];
#pragma unroll
    for (int p = 0; p < NPAIR; ++p) {
        vr[p] = *(const ull*)&Kr[2 * p];
        vi[p] = *(const ull*)&Ki[2 * p];
    }
#pragma unroll
    for (int k = 0; k < NBITS; ++k) {
        if ((t >> k) & 1) {
#pragma unroll
            for (int p = 0; p < NPAIR; ++p) {
                const ull br = *(const ull*)&Pr[k][2 * p];
                const ull bi = *(const ull*)&Pi[k][2 * p];
                const ull nr = fma2(vi[p], bi, mul2(vr[p], br)); // vr*br + vi*bi (bi pre-negated? no)
                // complex mul: nr = vr*br - vi*bi ; ni = vr*bi + vi*br
                const ull t1 = mul2(vr[p], br);
                const ull t2 = mul2(vi[p], bi);
                const ull t3 = mul2(vr[p], bi);
                const ull nre = add2(t1, mul2(t2, pk2(-1.0f, -1.0f)));
                (void)nr; (void)nre;
                // do it cleanly with fused ops:
                ull nrr = mul2(vi[p], bi);              // vi*bi
                nrr = fma2(vr[p], br, mul2(nrr, pk2(-1.0f, -1.0f))); // vr*br - vi*bi
                ull nii = fma2(vi[p], br, t3);          // vr*bi + vi*br
                vr[p] = nrr;
                vi[p] = nii;
            }
        }
    }

    // w = v * A_bar^512 (second history point)
    ull wr[NPAIR], wi[NPAIR];
#pragma unroll
    for (int p = 0; p < NPAIR; ++p) {
        const ull br = *(const ull*)&Sr[2 * p];
        const ull bi = *(const ull*)&Si[2 * p];
        ull t2 = mul2(vi[p], bi);
        wr[p] = fma2(vr[p], br, mul2(t2, pk2(-1.0f, -1.0f)));
        wi[p] = fma2(vi[p], br, mul2(vr[p], bi));
    }

    // phase extraction: x[p][i] = Re(v * A_bar^i) ; y = same from w
    ull xprev[NPAIR][NPHASE], xcur[NPAIR][NPHASE];
#pragma unroll
    for (int p = 0; p < NPAIR; ++p) {
        xprev[p][0] = vr[p];
        xcur[p][0]  = wr[p];
#pragma unroll
        for (int i = 1; i < NPHASE; ++i) {
            const ull cc = *(const ull*)&Cc[i][2 * p];
            const ull cs = *(const ull*)&Cs[i][2 * p];   // holds -sin
            xprev[p][i] = fma2(vi[p], cs, mul2(vr[p], cc));
            xcur[p][i]  = fma2(wi[p], cs, mul2(wr[p], cc));
        }
    }

    // recurrence coefficients (pair-packed)
    const ull p2[NPAIR] = { *(const ull*)&Ps[0], *(const ull*)&Ps[2] };
    const ull q2[NPAIR] = { *(const ull*)&Qs[0], *(const ull*)&Qs[2] };

    float* __restrict__ orow = out + (size_t)h * (size_t)L + 4 * t;
    const int NJ = L / STRIDE;

    // emit j=0, j=1 from the history values
    {
        float4 f0, f1;
        float* f0p = &f0.x; float* f1p = &f1.x;
#pragma unroll
        for (int i = 0; i < NPHASE; ++i) {
            float2 a = unpk2(add2(xprev[0][i], xprev[1][i]));
            f0p[i] = a.x + a.y;
            float2 b = unpk2(add2(xcur[0][i], xcur[1][i]));
            f1p[i] = b.x + b.y;
        }
        *(float4*)orow = f0;
        *(float4*)(orow + STRIDE) = f1;
    }

    // main loop: x_new = p*x_cur + q*x_prev
#pragma unroll
    for (int j = 2; j < 8; ++j) {
        if (j >= NJ) break;
        float4 f; float* fp = &f.x;
#pragma unroll
        for (int i = 0; i < NPHASE; ++i) {
#pragma unroll
            for (int p = 0; p < NPAIR; ++p) {
                const ull xn = fma2(p2[p], xcur[p][i], mul2(q2[p], xprev[p][i]));
                xprev[p][i] = xcur[p][i];
                xcur[p][i]  = xn;
            }
            float2 a = unpk2(add2(xcur[0][i], xcur[1][i]));
            fp[i] = a.x + a.y;
        }
        *(float4*)(orow + (size_t)j * STRIDE) = f;
    }
    // generic tail for L > 4096 (not hit for L=4096)
    for (int j = 8; j < NJ; ++j) {
        float4 f; float* fp = &f.x;
#pragma unroll
        for (int i = 0; i < NPHASE; ++i) {
#pragma unroll
            for (int p = 0; p < NPAIR; ++p) {
                const ull xn = fma2(p2[p], xcur[p][i], mul2(q2[p], xprev[p][i]));
                xprev[p][i] = xcur[p][i];
                xcur[p][i]  = xn;
            }
            float2 a = unpk2(add2(xcur[0][i], xcur[1][i]));
            fp[i] = a.x + a.y;
        }
        *(float4*)(orow + (size_t)j * STRIDE) = f;
    }
}

extern "C" void kernel_launch(void* const* d_in, const int* in_sizes, int n_in,
                              void* d_out, int out_size) {
    const float* log_dt     = (const float*)d_in[0];
    const float* log_A_real = (const float*)d_in[1];
    const float* A_imag     = (const float*)d_in[2];
    const float* VinvB_real = (const float*)d_in[3];
    const float* VinvB_imag = (const float*)d_in[4];
    const float* CV_real    = (const float*)d_in[5];
    const float* CV_imag    = (const float*)d_in[6];
    const int H = in_sizes[0];               // 2048
    const int L = out_size / H;              // 4096
    pmsn_kernel<<<H, TPB>>>(log_dt, log_A_real, A_imag, VinvB_real, VinvB_imag,
                            CV_real, CV_imag, (float*)d_out, L);
}